// round 13
// baseline (speedup 1.0000x reference)
#include <cuda_runtime.h>

// HyperPatch: b=16, c=8, h=w=512, fh=fw=16, c_out=8, sc=64, K=3, PAD=1
// R11 (3rd submit; infra failures R11/R12): FUSED single kernel. Each CTA
//      (one 32x32 tile) computes its own 576 hyper-weights (dot of w_s2w rows
//      with the tile's 64-float s-vector), then runs the PROVEN R4 conv inner
//      loop unchanged (register pack2, co-pairs f32x2, 256 thr,
//      launch_bounds(256,4) -> 64 regs, 4 CTAs/SM). Removes kernel-1 launch,
//      inter-kernel gap, and the g_wpp HBM round-trip.

#define N_TILES 4096

// ---- f32x2 helpers ---------------------------------------------------------
__device__ __forceinline__ unsigned long long ffma2(
    unsigned long long a, unsigned long long b, unsigned long long c)
{
    unsigned long long d;
    asm("fma.rn.f32x2 %0, %1, %2, %3;" : "=l"(d) : "l"(a), "l"(b), "l"(c));
    return d;
}
__device__ __forceinline__ unsigned long long pack2(float x)
{
    unsigned long long d;
    asm("mov.b64 %0, {%1, %1};" : "=l"(d) : "f"(x));
    return d;
}
__device__ __forceinline__ void unpack2(unsigned long long v, float& lo, float& hi)
{
    asm("mov.b64 {%0, %1}, %2;" : "=f"(lo), "=f"(hi) : "l"(v));
}

// ---------------------------------------------------------------------------
// Fused kernel. grid = 4096 tiles, 256 threads.
// Phase 1: stage s-vec (64 floats) + 34x34x8 reflect-padded window.
// Phase 2: weight-gen: o = t, t+256, t+512(<576): Wpp[o] = dot64(w_s2w[o], s)
//          stored transposed into wsm[o%72][o/72].
// Phase 3: R4 conv loop: 4 c_out (half = t>>7) x 8 px, 2 co-pair x 8 px f32x2.
// ---------------------------------------------------------------------------
__global__ __launch_bounds__(256, 4) void hyper_fused_kernel(
    const float* __restrict__ x,       // [16][8][512][512]
    const float* __restrict__ s_in,    // [16][64][256]
    const float* __restrict__ w_s2w,   // [576][64]
    float* __restrict__ out)           // [16][8][512][512]
{
    __shared__ float sin_s[8][34][36];            // 38.25 KB
    __shared__ __align__(16) float wsm[72][8];    // 2.25 KB
    __shared__ __align__(16) float svec[64];      // 256 B

    const int n  = blockIdx.x;
    const int t  = threadIdx.x;
    const int b  = n >> 8;
    const int fy = (n >> 4) & 15;
    const int fx = n & 15;
    const int fyfx = n & 255;

    // ---- Phase 1a: s-vector (warps 0-1), issued first so gmem lat overlaps
    if (t < 64)
        svec[t] = __ldg(s_in + b * 16384 + t * 256 + fyfx);

    // ---- Phase 1b: window staging (all threads)
    const float* xb  = x + (size_t)b * (8 * 512 * 512);
    const int row0 = fy * 32 - 1;
    const int col0 = fx * 32 - 1;
    for (int i = t; i < 8 * 34 * 34; i += 256) {
        int ci  = i / 1156;
        int rem = i - ci * 1156;
        int r   = rem / 34;
        int cl  = rem - r * 34;
        int gr = row0 + r;  gr = gr < 0 ? -gr : (gr > 511 ? 1022 - gr : gr);
        int gc = col0 + cl; gc = gc < 0 ? -gc : (gc > 511 ? 1022 - gc : gc);
        sin_s[ci][r][cl] = xb[(ci << 18) + (gr << 9) + gc];
    }
    __syncthreads();   // svec ready (window also done; single sync)

    // ---- Phase 2: per-tile hyper-weights, o = t, t+256, t+512
#pragma unroll
    for (int oo = 0; oo < 3; oo++) {
        int o = t + oo * 256;
        if (o < 576) {
            const float4* wr = reinterpret_cast<const float4*>(w_s2w + (size_t)o * 64);
            const float4* sv = reinterpret_cast<const float4*>(svec);
            float acc = 0.f;
#pragma unroll
            for (int k = 0; k < 16; k++) {
                float4 wv = __ldg(wr + k);
                float4 s4 = sv[k];
                acc = fmaf(wv.x, s4.x, acc);
                acc = fmaf(wv.y, s4.y, acc);
                acc = fmaf(wv.z, s4.z, acc);
                acc = fmaf(wv.w, s4.w, acc);
            }
            int co   = o / 72;
            int kidx = o - co * 72;
            wsm[kidx][co] = acc;
        }
    }
    __syncthreads();

    // ---- Phase 3: R4 conv loop (unchanged)
    const int cohalf = t >> 7;          // 0: co 0-3, 1: co 4-7
    const int tt  = t & 127;
    const int py  = tt >> 2;            // 0..31
    const int px0 = (tt & 3) << 3;      // 0,8,16,24

    unsigned long long acc2[2][8];      // [co-pair within half][pixel]
#pragma unroll
    for (int cp = 0; cp < 2; cp++)
#pragma unroll
        for (int p = 0; p < 8; p++) acc2[cp][p] = 0ull;

#pragma unroll 1
    for (int ci = 0; ci < 8; ci++) {
#pragma unroll
        for (int kr = 0; kr < 3; kr++) {
            const float* rowp = &sin_s[ci][py + kr][px0];
            float4 A  = *reinterpret_cast<const float4*>(rowp);
            float4 B  = *reinterpret_cast<const float4*>(rowp + 4);
            float2 Cc = *reinterpret_cast<const float2*>(rowp + 8);
            unsigned long long in2[10];
            in2[0] = pack2(A.x);  in2[1] = pack2(A.y);
            in2[2] = pack2(A.z);  in2[3] = pack2(A.w);
            in2[4] = pack2(B.x);  in2[5] = pack2(B.y);
            in2[6] = pack2(B.z);  in2[7] = pack2(B.w);
            in2[8] = pack2(Cc.x); in2[9] = pack2(Cc.y);
#pragma unroll
            for (int kc = 0; kc < 3; kc++) {
                const ulonglong2* wr2 =
                    reinterpret_cast<const ulonglong2*>(&wsm[ci * 9 + kr * 3 + kc][cohalf * 4]);
                ulonglong2 wA = wr2[0];   // co-pairs (0,1),(2,3) of this half
#pragma unroll
                for (int p = 0; p < 8; p++) {
                    acc2[0][p] = ffma2(wA.x, in2[kc + p], acc2[0][p]);
                    acc2[1][p] = ffma2(wA.y, in2[kc + p], acc2[1][p]);
                }
            }
        }
    }

    const int gy = (fy << 5) + py;
    const int gx = (fx << 5) + px0;
    const int co_base = b * 8 + cohalf * 4;
#pragma unroll
    for (int cp = 0; cp < 2; cp++) {
        float lo[8], hi[8];
#pragma unroll
        for (int p = 0; p < 8; p++) unpack2(acc2[cp][p], lo[p], hi[p]);
        float* op0 = out + (((size_t)(co_base + 2 * cp))     << 18) + (gy << 9) + gx;
        float* op1 = out + (((size_t)(co_base + 2 * cp + 1)) << 18) + (gy << 9) + gx;
        *reinterpret_cast<float4*>(op0)     = make_float4(lo[0], lo[1], lo[2], lo[3]);
        *reinterpret_cast<float4*>(op0 + 4) = make_float4(lo[4], lo[5], lo[6], lo[7]);
        *reinterpret_cast<float4*>(op1)     = make_float4(hi[0], hi[1], hi[2], hi[3]);
        *reinterpret_cast<float4*>(op1 + 4) = make_float4(hi[4], hi[5], hi[6], hi[7]);
    }
}

// ---------------------------------------------------------------------------
extern "C" void kernel_launch(void* const* d_in, const int* in_sizes, int n_in,
                              void* d_out, int out_size)
{
    (void)in_sizes; (void)n_in; (void)out_size;
    const float* x     = (const float*)d_in[0];   // [16,8,512,512]
    const float* s     = (const float*)d_in[1];   // [16,64,16,16]
    const float* w_s2w = (const float*)d_in[2];   // [576,64]
    float* out = (float*)d_out;                   // [16,8,512,512]

    hyper_fused_kernel<<<N_TILES, 256>>>(x, s, w_s2w, out);
}

// round 15
// speedup vs baseline: 1.4599x; 1.4599x over previous
#include <cuda_runtime.h>

// HyperPatch: b=16, c=8, h=w=512, fh=fw=16, c_out=8, sc=64, K=3, PAD=1
// R14 (resubmit; infra failure): conv = PROVEN R4 kernel (register pack2,
//      co-pairs f32x2, 256 thr, launch_bounds(256,4), 64 regs, 4 CTAs/SM)
//      -- unchanged. kernel1 = cheaper GEMM: grid (32,18), 32-o chunk staged
//      in smem, thread = 1 n x 16 o (4 broadcast LDS.128 + 16 FFMA per s),
//      s re-read 18x instead of 72x.

#define N_TILES 4096
__device__ float g_wpp[N_TILES * 576];   // scratch: [n][o]

// ---- f32x2 helpers ---------------------------------------------------------
__device__ __forceinline__ unsigned long long ffma2(
    unsigned long long a, unsigned long long b, unsigned long long c)
{
    unsigned long long d;
    asm("fma.rn.f32x2 %0, %1, %2, %3;" : "=l"(d) : "l"(a), "l"(b), "l"(c));
    return d;
}
__device__ __forceinline__ unsigned long long pack2(float x)
{
    unsigned long long d;
    asm("mov.b64 %0, {%1, %1};" : "=l"(d) : "f"(x));
    return d;
}
__device__ __forceinline__ void unpack2(unsigned long long v, float& lo, float& hi)
{
    asm("mov.b64 {%0, %1}, %2;" : "=f"(lo), "=f"(hi) : "l"(v));
}

// ---------------------------------------------------------------------------
// Kernel 1: g_wpp[4096 x 576] = S[4096 x 64] @ w_s2w^T
// grid (32, 18), 256 threads. CTA: 128 n x 32 o. Thread: 1 n x 16 o.
// ---------------------------------------------------------------------------
__global__ __launch_bounds__(256) void hyper_weights_kernel(
    const float* __restrict__ w_s2w,   // [576][64]
    const float* __restrict__ s_in)    // [16][64][256]
{
    __shared__ __align__(16) float wsm[64][32];   // [s][o-local], 8 KB

    const int t  = threadIdx.x;
    const int n0 = blockIdx.x * 128;
    const int o0 = blockIdx.y * 32;
    const int b  = n0 >> 8;
    const int f0 = n0 & 255;

    // stage 32 o-rows of w_s2w, transposed to [s][o]
#pragma unroll
    for (int i = t; i < 2048; i += 256) {
        int o = i >> 6;
        int s = i & 63;
        wsm[s][o] = w_s2w[(size_t)(o0 + o) * 64 + s];
    }
    __syncthreads();

    const int tn = t & 127;        // n-local
    const int to = t >> 7;         // o-half: 0 -> o 0..15, 1 -> o 16..31
    const float* sp = s_in + b * 16384 + f0 + tn;

    float acc[16];
#pragma unroll
    for (int k = 0; k < 16; k++) acc[k] = 0.f;

#pragma unroll 4
    for (int s = 0; s < 64; s++) {
        float a = __ldg(sp + s * 256);   // coalesced across lanes
        const float4* wr = reinterpret_cast<const float4*>(&wsm[s][to * 16]);
#pragma unroll
        for (int j = 0; j < 4; j++) {
            float4 w = wr[j];            // warp-uniform -> LDS.128 broadcast
            acc[4 * j]     = fmaf(w.x, a, acc[4 * j]);
            acc[4 * j + 1] = fmaf(w.y, a, acc[4 * j + 1]);
            acc[4 * j + 2] = fmaf(w.z, a, acc[4 * j + 2]);
            acc[4 * j + 3] = fmaf(w.w, a, acc[4 * j + 3]);
        }
    }

    float4* dst = reinterpret_cast<float4*>(
        g_wpp + (size_t)(n0 + tn) * 576 + o0 + to * 16);
#pragma unroll
    for (int j = 0; j < 4; j++)
        dst[j] = make_float4(acc[4 * j], acc[4 * j + 1],
                             acc[4 * j + 2], acc[4 * j + 3]);
}

// ---------------------------------------------------------------------------
// Kernel 2: per-tile 3x3 conv (PROVEN R4). grid = 4096 tiles, 256 threads.
// Thread: 4 c_out (half = t>>7) x 8 px, acc as 2 co-pair x 8 px f32x2.
// smem: input [8ci][34][36] plain f32, weights [kidx=72][co=8].
// ---------------------------------------------------------------------------
__global__ __launch_bounds__(256, 4) void hyper_conv_kernel(
    const float* __restrict__ x,       // [16][8][512][512]
    float* __restrict__ out)           // [16][8][512][512]
{
    __shared__ float sin_s[8][34][36];
    __shared__ __align__(16) float wsm[72][8];

    const int n  = blockIdx.x;
    const int t  = threadIdx.x;
    const int b  = n >> 8;
    const int fy = (n >> 4) & 15;
    const int fx = n & 15;

    // stage weights: g_wpp[n][co*72 + kidx] -> wsm[kidx][co]
    const float* wpp_n = g_wpp + (size_t)n * 576;
    for (int i = t; i < 576; i += 256) {
        int co   = i / 72;
        int kidx = i - co * 72;
        wsm[kidx][co] = wpp_n[i];
    }

    // stage 34x34x8 reflect-padded input window
    const float* xb  = x + (size_t)b * (8 * 512 * 512);
    const int row0 = fy * 32 - 1;
    const int col0 = fx * 32 - 1;
    for (int i = t; i < 8 * 34 * 34; i += 256) {
        int ci  = i / 1156;
        int rem = i - ci * 1156;
        int r   = rem / 34;
        int cl  = rem - r * 34;
        int gr = row0 + r;  gr = gr < 0 ? -gr : (gr > 511 ? 1022 - gr : gr);
        int gc = col0 + cl; gc = gc < 0 ? -gc : (gc > 511 ? 1022 - gc : gc);
        sin_s[ci][r][cl] = xb[(ci << 18) + (gr << 9) + gc];
    }
    __syncthreads();

    const int cohalf = t >> 7;          // 0: co 0-3, 1: co 4-7
    const int tt  = t & 127;
    const int py  = tt >> 2;            // 0..31
    const int px0 = (tt & 3) << 3;      // 0,8,16,24

    unsigned long long acc2[2][8];      // [co-pair within half][pixel]
#pragma unroll
    for (int cp = 0; cp < 2; cp++)
#pragma unroll
        for (int p = 0; p < 8; p++) acc2[cp][p] = 0ull;

#pragma unroll 1
    for (int ci = 0; ci < 8; ci++) {
#pragma unroll
        for (int kr = 0; kr < 3; kr++) {
            const float* rowp = &sin_s[ci][py + kr][px0];
            float4 A  = *reinterpret_cast<const float4*>(rowp);
            float4 B  = *reinterpret_cast<const float4*>(rowp + 4);
            float2 Cc = *reinterpret_cast<const float2*>(rowp + 8);
            unsigned long long in2[10];
            in2[0] = pack2(A.x);  in2[1] = pack2(A.y);
            in2[2] = pack2(A.z);  in2[3] = pack2(A.w);
            in2[4] = pack2(B.x);  in2[5] = pack2(B.y);
            in2[6] = pack2(B.z);  in2[7] = pack2(B.w);
            in2[8] = pack2(Cc.x); in2[9] = pack2(Cc.y);
#pragma unroll
            for (int kc = 0; kc < 3; kc++) {
                const ulonglong2* wr =
                    reinterpret_cast<const ulonglong2*>(&wsm[ci * 9 + kr * 3 + kc][cohalf * 4]);
                ulonglong2 wA = wr[0];   // co-pairs (0,1),(2,3) of this half
#pragma unroll
                for (int p = 0; p < 8; p++) {
                    acc2[0][p] = ffma2(wA.x, in2[kc + p], acc2[0][p]);
                    acc2[1][p] = ffma2(wA.y, in2[kc + p], acc2[1][p]);
                }
            }
        }
    }

    const int gy = (fy << 5) + py;
    const int gx = (fx << 5) + px0;
    const int co_base = b * 8 + cohalf * 4;
#pragma unroll
    for (int cp = 0; cp < 2; cp++) {
        float lo[8], hi[8];
#pragma unroll
        for (int p = 0; p < 8; p++) unpack2(acc2[cp][p], lo[p], hi[p]);
        float* op0 = out + (((size_t)(co_base + 2 * cp))     << 18) + (gy << 9) + gx;
        float* op1 = out + (((size_t)(co_base + 2 * cp + 1)) << 18) + (gy << 9) + gx;
        *reinterpret_cast<float4*>(op0)     = make_float4(lo[0], lo[1], lo[2], lo[3]);
        *reinterpret_cast<float4*>(op0 + 4) = make_float4(lo[4], lo[5], lo[6], lo[7]);
        *reinterpret_cast<float4*>(op1)     = make_float4(hi[0], hi[1], hi[2], hi[3]);
        *reinterpret_cast<float4*>(op1 + 4) = make_float4(hi[4], hi[5], hi[6], hi[7]);
    }
}

// ---------------------------------------------------------------------------
extern "C" void kernel_launch(void* const* d_in, const int* in_sizes, int n_in,
                              void* d_out, int out_size)
{
    (void)in_sizes; (void)n_in; (void)out_size;
    const float* x     = (const float*)d_in[0];   // [16,8,512,512]
    const float* s     = (const float*)d_in[1];   // [16,64,16,16]
    const float* w_s2w = (const float*)d_in[2];   // [576,64]
    float* out = (float*)d_out;                   // [16,8,512,512]

    hyper_weights_kernel<<<dim3(32, 18), 256>>>(w_s2w, s);
    hyper_conv_kernel<<<N_TILES, 256>>>(x, out);
}